// round 4
// baseline (speedup 1.0000x reference)
#include <cuda_runtime.h>
#include <cuda_bf16.h>

// Problem constants (verified against in_sizes at launch)
#define D        128
#define MAX_N    100000

// Scratch for h = x @ W^T  (51.2 MB) — __device__ global per allocation rules.
__device__ float g_h[(size_t)MAX_N * D];

// ---------------------------------------------------------------------------
// Kernel 1: h = x @ W^T   (fp32 SIMT, W transposed in smem, 4x4 microtile)
// Block: 256 threads (8 warps). Each block computes 32 rows.
// Each warp computes 4 rows; lane computes cols [lane*4, lane*4+4).
// ---------------------------------------------------------------------------
#define WT_LD 132                         // 128 + 4 pad: 16B-aligned rows, reduced store conflicts
#define GEMM_SMEM_BYTES ((128 * WT_LD + 32 * 128) * 4)

__global__ void __launch_bounds__(256, 2)
gemm_kernel(const float* __restrict__ x, const float* __restrict__ W, int N) {
    extern __shared__ float smem[];
    float* Wt = smem;                 // [128][WT_LD]  Wt[k][c] = W[c][k]
    float* xs = smem + 128 * WT_LD;   // [32][128]

    const int tid = threadIdx.x;
    const int row0 = blockIdx.x * 32;

    // Stage W transposed (coalesced global reads)
    #pragma unroll 4
    for (int i = tid; i < 128 * 128; i += 256) {
        int c = i >> 7, k = i & 127;
        Wt[k * WT_LD + c] = W[i];
    }
    // Stage 32 rows of x (N is a multiple of 32 here: 100000 = 3125*32)
    #pragma unroll 4
    for (int i = tid; i < 32 * 128; i += 256) {
        xs[i] = x[(size_t)row0 * D + i];
    }
    __syncthreads();

    const int warp = tid >> 5, lane = tid & 31;
    const int r0 = warp * 4;           // 4 rows per warp
    const int c0 = lane * 4;           // 4 cols per lane

    float4 acc0 = {0.f,0.f,0.f,0.f};
    float4 acc1 = {0.f,0.f,0.f,0.f};
    float4 acc2 = {0.f,0.f,0.f,0.f};
    float4 acc3 = {0.f,0.f,0.f,0.f};

    #pragma unroll 8
    for (int k0 = 0; k0 < 128; k0 += 4) {
        float4 wv0 = *(const float4*)&Wt[(k0 + 0) * WT_LD + c0];
        float4 wv1 = *(const float4*)&Wt[(k0 + 1) * WT_LD + c0];
        float4 wv2 = *(const float4*)&Wt[(k0 + 2) * WT_LD + c0];
        float4 wv3 = *(const float4*)&Wt[(k0 + 3) * WT_LD + c0];

        float4 xv0 = *(const float4*)&xs[(r0 + 0) * 128 + k0];
        float4 xv1 = *(const float4*)&xs[(r0 + 1) * 128 + k0];
        float4 xv2 = *(const float4*)&xs[(r0 + 2) * 128 + k0];
        float4 xv3 = *(const float4*)&xs[(r0 + 3) * 128 + k0];

        #define STEP(ACC, XV)                                            \
            ACC.x += XV.x * wv0.x; ACC.y += XV.x * wv0.y;                 \
            ACC.z += XV.x * wv0.z; ACC.w += XV.x * wv0.w;                 \
            ACC.x += XV.y * wv1.x; ACC.y += XV.y * wv1.y;                 \
            ACC.z += XV.y * wv1.z; ACC.w += XV.y * wv1.w;                 \
            ACC.x += XV.z * wv2.x; ACC.y += XV.z * wv2.y;                 \
            ACC.z += XV.z * wv2.z; ACC.w += XV.z * wv2.w;                 \
            ACC.x += XV.w * wv3.x; ACC.y += XV.w * wv3.y;                 \
            ACC.z += XV.w * wv3.z; ACC.w += XV.w * wv3.w;
        STEP(acc0, xv0)
        STEP(acc1, xv1)
        STEP(acc2, xv2)
        STEP(acc3, xv3)
        #undef STEP
    }

    float4* hp = (float4*)&g_h[(size_t)(row0 + r0) * D + c0];
    hp[0]            = acc0;
    hp[D / 4]        = acc1;
    hp[2 * (D / 4)]  = acc2;
    hp[3 * (D / 4)]  = acc3;
}

// ---------------------------------------------------------------------------
// Kernel 2: scatter-sum.  out[dst] += h[src] for every edge.
// Block: 256 threads, EPB edges. Indices staged in smem (coalesced loads),
// one warp per edge-iteration: lane gathers float4 of h[src], vector-reduces
// into out[dst] via red.global.add.v4.f32 (16B atomic, no return).
// ---------------------------------------------------------------------------
#define EPB 2048

__global__ void __launch_bounds__(256)
scatter_kernel(const int* __restrict__ ei, float* __restrict__ out, int E) {
    __shared__ int s_src[EPB];
    __shared__ int s_dst[EPB];

    const int base = blockIdx.x * EPB;
    const int n = min(EPB, E - base);

    for (int i = threadIdx.x; i < n; i += 256) {
        s_src[i] = ei[base + i];        // edge_index[0][.]
        s_dst[i] = ei[E + base + i];    // edge_index[1][.]
    }
    __syncthreads();

    const int warp = threadIdx.x >> 5;
    const int lane = threadIdx.x & 31;

    const int start = warp * (EPB / 8);
    const int end = min(start + (EPB / 8), n);

    for (int e = start; e < end; e++) {
        int src = s_src[e];             // LDS broadcast
        int dst = s_dst[e];

        const float4* hp = (const float4*)&g_h[(size_t)src * D] + lane;
        float4 v = __ldg(hp);

        float* op = out + (size_t)dst * D + lane * 4;
        asm volatile("red.global.add.v4.f32 [%0], {%1, %2, %3, %4};"
                     :: "l"(op), "f"(v.x), "f"(v.y), "f"(v.z), "f"(v.w)
                     : "memory");
    }
}

// ---------------------------------------------------------------------------
extern "C" void kernel_launch(void* const* d_in, const int* in_sizes, int n_in,
                              void* d_out, int out_size) {
    const float* x  = (const float*)d_in[0];   // [N, 128] fp32
    const float* W  = (const float*)d_in[1];   // [128, 128] fp32
    const int*   ei = (const int*)d_in[2];     // [2, E] int32
    float* out = (float*)d_out;                // [N, 128] fp32

    const int N = in_sizes[0] / D;
    const int E = in_sizes[2] / 2;

    // Opt in to 84KB dynamic smem for the GEMM (idempotent, capture-safe).
    cudaFuncSetAttribute(gemm_kernel,
                         cudaFuncAttributeMaxDynamicSharedMemorySize,
                         GEMM_SMEM_BYTES);

    // out must start at zero (harness poisons it).
    cudaMemsetAsync(d_out, 0, (size_t)out_size * sizeof(float), 0);

    gemm_kernel<<<N / 32, 256, GEMM_SMEM_BYTES>>>(x, W, N);

    int nblocks = (E + EPB - 1) / EPB;
    scatter_kernel<<<nblocks, 256>>>(ei, out, E);
}

// round 5
// speedup vs baseline: 1.0006x; 1.0006x over previous
#include <cuda_runtime.h>
#include <cuda_bf16.h>

// Problem constants (verified against in_sizes at launch)
#define D        128
#define MAX_N    100000

// Scratch for h = x @ W^T  (51.2 MB) — __device__ global per allocation rules.
__device__ float g_h[(size_t)MAX_N * D];

// ---------------------------------------------------------------------------
// Kernel 1: h = x @ W^T   (fp32 SIMT, W transposed in smem, 4x4 microtile)
// Block: 256 threads (8 warps). Each block computes 32 rows.
// Each warp computes 4 rows; lane computes cols [lane*4, lane*4+4).
// ---------------------------------------------------------------------------
#define WT_LD 132                         // 128 + 4 pad: 16B-aligned rows, reduced store conflicts
#define GEMM_SMEM_BYTES ((128 * WT_LD + 32 * 128) * 4)

__global__ void __launch_bounds__(256, 2)
gemm_kernel(const float* __restrict__ x, const float* __restrict__ W, int N) {
    extern __shared__ float smem[];
    float* Wt = smem;                 // [128][WT_LD]  Wt[k][c] = W[c][k]
    float* xs = smem + 128 * WT_LD;   // [32][128]

    const int tid = threadIdx.x;
    const int row0 = blockIdx.x * 32;

    // Stage W transposed (coalesced global reads)
    #pragma unroll 4
    for (int i = tid; i < 128 * 128; i += 256) {
        int c = i >> 7, k = i & 127;
        Wt[k * WT_LD + c] = W[i];
    }
    // Stage 32 rows of x (N is a multiple of 32 here: 100000 = 3125*32)
    #pragma unroll 4
    for (int i = tid; i < 32 * 128; i += 256) {
        xs[i] = x[(size_t)row0 * D + i];
    }
    __syncthreads();

    const int warp = tid >> 5, lane = tid & 31;
    const int r0 = warp * 4;           // 4 rows per warp
    const int c0 = lane * 4;           // 4 cols per lane

    float4 acc0 = {0.f,0.f,0.f,0.f};
    float4 acc1 = {0.f,0.f,0.f,0.f};
    float4 acc2 = {0.f,0.f,0.f,0.f};
    float4 acc3 = {0.f,0.f,0.f,0.f};

    #pragma unroll 8
    for (int k0 = 0; k0 < 128; k0 += 4) {
        float4 wv0 = *(const float4*)&Wt[(k0 + 0) * WT_LD + c0];
        float4 wv1 = *(const float4*)&Wt[(k0 + 1) * WT_LD + c0];
        float4 wv2 = *(const float4*)&Wt[(k0 + 2) * WT_LD + c0];
        float4 wv3 = *(const float4*)&Wt[(k0 + 3) * WT_LD + c0];

        float4 xv0 = *(const float4*)&xs[(r0 + 0) * 128 + k0];
        float4 xv1 = *(const float4*)&xs[(r0 + 1) * 128 + k0];
        float4 xv2 = *(const float4*)&xs[(r0 + 2) * 128 + k0];
        float4 xv3 = *(const float4*)&xs[(r0 + 3) * 128 + k0];

        #define STEP(ACC, XV)                                            \
            ACC.x += XV.x * wv0.x; ACC.y += XV.x * wv0.y;                 \
            ACC.z += XV.x * wv0.z; ACC.w += XV.x * wv0.w;                 \
            ACC.x += XV.y * wv1.x; ACC.y += XV.y * wv1.y;                 \
            ACC.z += XV.y * wv1.z; ACC.w += XV.y * wv1.w;                 \
            ACC.x += XV.z * wv2.x; ACC.y += XV.z * wv2.y;                 \
            ACC.z += XV.z * wv2.z; ACC.w += XV.z * wv2.w;                 \
            ACC.x += XV.w * wv3.x; ACC.y += XV.w * wv3.y;                 \
            ACC.z += XV.w * wv3.z; ACC.w += XV.w * wv3.w;
        STEP(acc0, xv0)
        STEP(acc1, xv1)
        STEP(acc2, xv2)
        STEP(acc3, xv3)
        #undef STEP
    }

    float4* hp = (float4*)&g_h[(size_t)(row0 + r0) * D + c0];
    hp[0]            = acc0;
    hp[D / 4]        = acc1;
    hp[2 * (D / 4)]  = acc2;
    hp[3 * (D / 4)]  = acc3;
}

// ---------------------------------------------------------------------------
// Kernel 2: scatter-sum.  out[dst] += h[src] for every edge.
// Block: 256 threads, EPB edges. Indices staged in smem (coalesced loads),
// one warp per edge-iteration: lane gathers float4 of h[src], vector-reduces
// into out[dst] via red.global.add.v4.f32 (16B atomic, no return).
// ---------------------------------------------------------------------------
#define EPB 2048

__global__ void __launch_bounds__(256)
scatter_kernel(const int* __restrict__ ei, float* __restrict__ out, int E) {
    __shared__ int s_src[EPB];
    __shared__ int s_dst[EPB];

    const int base = blockIdx.x * EPB;
    const int n = min(EPB, E - base);

    for (int i = threadIdx.x; i < n; i += 256) {
        s_src[i] = ei[base + i];        // edge_index[0][.]
        s_dst[i] = ei[E + base + i];    // edge_index[1][.]
    }
    __syncthreads();

    const int warp = threadIdx.x >> 5;
    const int lane = threadIdx.x & 31;

    const int start = warp * (EPB / 8);
    const int end = min(start + (EPB / 8), n);

    for (int e = start; e < end; e++) {
        int src = s_src[e];             // LDS broadcast
        int dst = s_dst[e];

        const float4* hp = (const float4*)&g_h[(size_t)src * D] + lane;
        float4 v = __ldg(hp);

        float* op = out + (size_t)dst * D + lane * 4;
        asm volatile("red.global.add.v4.f32 [%0], {%1, %2, %3, %4};"
                     :: "l"(op), "f"(v.x), "f"(v.y), "f"(v.z), "f"(v.w)
                     : "memory");
    }
}

// ---------------------------------------------------------------------------
extern "C" void kernel_launch(void* const* d_in, const int* in_sizes, int n_in,
                              void* d_out, int out_size) {
    const float* x  = (const float*)d_in[0];   // [N, 128] fp32
    const float* W  = (const float*)d_in[1];   // [128, 128] fp32
    const int*   ei = (const int*)d_in[2];     // [2, E] int32
    float* out = (float*)d_out;                // [N, 128] fp32

    const int N = in_sizes[0] / D;
    const int E = in_sizes[2] / 2;

    // Opt in to 84KB dynamic smem for the GEMM (idempotent, capture-safe).
    cudaFuncSetAttribute(gemm_kernel,
                         cudaFuncAttributeMaxDynamicSharedMemorySize,
                         GEMM_SMEM_BYTES);

    // out must start at zero (harness poisons it).
    cudaMemsetAsync(d_out, 0, (size_t)out_size * sizeof(float), 0);

    gemm_kernel<<<N / 32, 256, GEMM_SMEM_BYTES>>>(x, W, N);

    int nblocks = (E + EPB - 1) / EPB;
    scatter_kernel<<<nblocks, 256>>>(ei, out, E);
}

// round 6
// speedup vs baseline: 1.3576x; 1.3567x over previous
#include <cuda_runtime.h>
#include <cuda_bf16.h>

// Problem constants (verified against in_sizes at launch)
#define D        128
#define MAX_N    100000
#define MAX_E    3200000
#define CHUNK    1024
#define MAX_BLK  ((MAX_N + CHUNK - 1) / CHUNK)   // 98

// Scratch (__device__ globals per allocation rules)
__device__ float g_h[(size_t)MAX_N * D];      // 51.2 MB: h = x @ W^T
__device__ int   g_count[MAX_N];              // per-dst degree
__device__ int   g_off[MAX_N + 1];            // exclusive offsets
__device__ int   g_cursor[MAX_N];             // fill cursors
__device__ int   g_bsum[MAX_BLK];             // per-block sums
__device__ int   g_boff[MAX_BLK];             // per-block offsets
__device__ int   g_binned_src[MAX_E];         // edges sorted by dst

// ---------------------------------------------------------------------------
// Kernel 1: h = x @ W^T   (fp32 SIMT, W transposed in smem, 4x4 microtile)
// ---------------------------------------------------------------------------
#define WT_LD 132
#define GEMM_SMEM_BYTES ((128 * WT_LD + 32 * 128) * 4)

__global__ void __launch_bounds__(256, 2)
gemm_kernel(const float* __restrict__ x, const float* __restrict__ W, int N) {
    extern __shared__ float smem[];
    float* Wt = smem;                 // [128][WT_LD]  Wt[k][c] = W[c][k]
    float* xs = smem + 128 * WT_LD;   // [32][128]

    const int tid = threadIdx.x;
    const int row0 = blockIdx.x * 32;

    #pragma unroll 4
    for (int i = tid; i < 128 * 128; i += 256) {
        int c = i >> 7, k = i & 127;
        Wt[k * WT_LD + c] = W[i];
    }
    #pragma unroll 4
    for (int i = tid; i < 32 * 128; i += 256) {
        xs[i] = x[(size_t)row0 * D + i];
    }
    __syncthreads();

    const int warp = tid >> 5, lane = tid & 31;
    const int r0 = warp * 4;
    const int c0 = lane * 4;

    float4 acc0 = {0.f,0.f,0.f,0.f};
    float4 acc1 = {0.f,0.f,0.f,0.f};
    float4 acc2 = {0.f,0.f,0.f,0.f};
    float4 acc3 = {0.f,0.f,0.f,0.f};

    #pragma unroll 8
    for (int k0 = 0; k0 < 128; k0 += 4) {
        float4 wv0 = *(const float4*)&Wt[(k0 + 0) * WT_LD + c0];
        float4 wv1 = *(const float4*)&Wt[(k0 + 1) * WT_LD + c0];
        float4 wv2 = *(const float4*)&Wt[(k0 + 2) * WT_LD + c0];
        float4 wv3 = *(const float4*)&Wt[(k0 + 3) * WT_LD + c0];

        float4 xv0 = *(const float4*)&xs[(r0 + 0) * 128 + k0];
        float4 xv1 = *(const float4*)&xs[(r0 + 1) * 128 + k0];
        float4 xv2 = *(const float4*)&xs[(r0 + 2) * 128 + k0];
        float4 xv3 = *(const float4*)&xs[(r0 + 3) * 128 + k0];

        #define STEP(ACC, XV)                                            \
            ACC.x += XV.x * wv0.x; ACC.y += XV.x * wv0.y;                 \
            ACC.z += XV.x * wv0.z; ACC.w += XV.x * wv0.w;                 \
            ACC.x += XV.y * wv1.x; ACC.y += XV.y * wv1.y;                 \
            ACC.z += XV.y * wv1.z; ACC.w += XV.y * wv1.w;                 \
            ACC.x += XV.z * wv2.x; ACC.y += XV.z * wv2.y;                 \
            ACC.z += XV.z * wv2.z; ACC.w += XV.z * wv2.w;                 \
            ACC.x += XV.w * wv3.x; ACC.y += XV.w * wv3.y;                 \
            ACC.z += XV.w * wv3.z; ACC.w += XV.w * wv3.w;
        STEP(acc0, xv0)
        STEP(acc1, xv1)
        STEP(acc2, xv2)
        STEP(acc3, xv3)
        #undef STEP
    }

    float4* hp = (float4*)&g_h[(size_t)(row0 + r0) * D + c0];
    hp[0]           = acc0;
    hp[D / 4]       = acc1;
    hp[2 * (D / 4)] = acc2;
    hp[3 * (D / 4)] = acc3;
}

// ---------------------------------------------------------------------------
// Binning pipeline: counting sort of edges by dst
// ---------------------------------------------------------------------------
__global__ void hist_kernel(const int* __restrict__ ei, int E) {
    int i = blockIdx.x * blockDim.x + threadIdx.x;
    int stride = gridDim.x * blockDim.x;
    for (; i < E; i += stride) {
        atomicAdd(&g_count[ei[E + i]], 1);   // dst row of edge_index
    }
}

// Per-chunk sums of g_count
__global__ void scan1_kernel(int N) {
    __shared__ int s[CHUNK];
    int i = blockIdx.x * CHUNK + threadIdx.x;
    s[threadIdx.x] = (i < N) ? g_count[i] : 0;
    __syncthreads();
    #pragma unroll
    for (int d = CHUNK / 2; d > 0; d >>= 1) {
        if (threadIdx.x < d) s[threadIdx.x] += s[threadIdx.x + d];
        __syncthreads();
    }
    if (threadIdx.x == 0) g_bsum[blockIdx.x] = s[0];
}

// Exclusive scan of block sums (NB <= 128, single block)
__global__ void scan2_kernel(int NB) {
    __shared__ int s[MAX_BLK + 1];
    if (threadIdx.x < NB) s[threadIdx.x] = g_bsum[threadIdx.x];
    __syncthreads();
    if (threadIdx.x == 0) {
        int run = 0;
        for (int b = 0; b < NB; b++) { int v = s[b]; s[b] = run; run += v; }
    }
    __syncthreads();
    if (threadIdx.x < NB) g_boff[threadIdx.x] = s[threadIdx.x];
}

// Per-chunk exclusive scan + base offset -> g_off, g_cursor
__global__ void scan3_kernel(int N) {
    __shared__ int buf0[CHUNK];
    __shared__ int buf1[CHUNK];
    int i = blockIdx.x * CHUNK + threadIdx.x;
    int val = (i < N) ? g_count[i] : 0;

    int* cur = buf0; int* nxt = buf1;
    cur[threadIdx.x] = val;
    __syncthreads();
    #pragma unroll
    for (int d = 1; d < CHUNK; d <<= 1) {             // Hillis-Steele inclusive
        int v = cur[threadIdx.x];
        if (threadIdx.x >= d) v += cur[threadIdx.x - d];
        nxt[threadIdx.x] = v;
        __syncthreads();
        int* t = cur; cur = nxt; nxt = t;
    }
    if (i < N) {
        int excl = cur[threadIdx.x] - val + g_boff[blockIdx.x];
        g_off[i]    = excl;
        g_cursor[i] = excl;
        if (i == N - 1) g_off[N] = excl + val;
    }
}

__global__ void binfill_kernel(const int* __restrict__ ei, int E) {
    int i = blockIdx.x * blockDim.x + threadIdx.x;
    int stride = gridDim.x * blockDim.x;
    for (; i < E; i += stride) {
        int src = ei[i];
        int dst = ei[E + i];
        int pos = atomicAdd(&g_cursor[dst], 1);
        g_binned_src[pos] = src;
    }
}

// ---------------------------------------------------------------------------
// Gather: one warp per destination node, no atomics, single coalesced store.
// Lanes cooperatively load up to 32 bin indices (coalesced), broadcast via
// shfl, accumulate 4-way-interleaved float4s of h rows.
// ---------------------------------------------------------------------------
__global__ void __launch_bounds__(256)
gather_kernel(float* __restrict__ out, int N) {
    const int node = blockIdx.x * 8 + (threadIdx.x >> 5);
    if (node >= N) return;
    const int lane = threadIdx.x & 31;

    const int s = __ldg(&g_off[node]);
    const int e = __ldg(&g_off[node + 1]);

    float4 a0 = {0.f,0.f,0.f,0.f};
    float4 a1 = {0.f,0.f,0.f,0.f};
    float4 a2 = {0.f,0.f,0.f,0.f};
    float4 a3 = {0.f,0.f,0.f,0.f};

    for (int j = s; j < e; j += 32) {
        const int m = min(32, e - j);
        int srcv = (j + lane < e) ? __ldg(&g_binned_src[j + lane]) : 0;

        int b = 0;
        for (; b + 4 <= m; b += 4) {
            int s0 = __shfl_sync(0xFFFFFFFFu, srcv, b);
            int s1 = __shfl_sync(0xFFFFFFFFu, srcv, b + 1);
            int s2 = __shfl_sync(0xFFFFFFFFu, srcv, b + 2);
            int s3 = __shfl_sync(0xFFFFFFFFu, srcv, b + 3);
            float4 v0 = __ldg((const float4*)&g_h[(size_t)s0 * D] + lane);
            float4 v1 = __ldg((const float4*)&g_h[(size_t)s1 * D] + lane);
            float4 v2 = __ldg((const float4*)&g_h[(size_t)s2 * D] + lane);
            float4 v3 = __ldg((const float4*)&g_h[(size_t)s3 * D] + lane);
            a0.x += v0.x; a0.y += v0.y; a0.z += v0.z; a0.w += v0.w;
            a1.x += v1.x; a1.y += v1.y; a1.z += v1.z; a1.w += v1.w;
            a2.x += v2.x; a2.y += v2.y; a2.z += v2.z; a2.w += v2.w;
            a3.x += v3.x; a3.y += v3.y; a3.z += v3.z; a3.w += v3.w;
        }
        for (; b < m; b++) {
            int sb = __shfl_sync(0xFFFFFFFFu, srcv, b);
            float4 v = __ldg((const float4*)&g_h[(size_t)sb * D] + lane);
            a0.x += v.x; a0.y += v.y; a0.z += v.z; a0.w += v.w;
        }
    }

    a0.x += a1.x + a2.x + a3.x;
    a0.y += a1.y + a2.y + a3.y;
    a0.z += a1.z + a2.z + a3.z;
    a0.w += a1.w + a2.w + a3.w;

    *((float4*)&out[(size_t)node * D] + lane) = a0;
}

// ---------------------------------------------------------------------------
extern "C" void kernel_launch(void* const* d_in, const int* in_sizes, int n_in,
                              void* d_out, int out_size) {
    const float* x  = (const float*)d_in[0];   // [N, 128] fp32
    const float* W  = (const float*)d_in[1];   // [128, 128] fp32
    const int*   ei = (const int*)d_in[2];     // [2, E] int32
    float* out = (float*)d_out;                // [N, 128] fp32

    const int N  = in_sizes[0] / D;
    const int E  = in_sizes[2] / 2;
    const int NB = (N + CHUNK - 1) / CHUNK;

    cudaFuncSetAttribute(gemm_kernel,
                         cudaFuncAttributeMaxDynamicSharedMemorySize,
                         GEMM_SMEM_BYTES);

    // Zero the degree histogram (capture-safe: memset on a symbol address).
    void* count_ptr = nullptr;
    cudaGetSymbolAddress(&count_ptr, g_count);
    cudaMemsetAsync(count_ptr, 0, (size_t)N * sizeof(int), 0);

    // GEMM: h = x @ W^T
    gemm_kernel<<<N / 32, 256, GEMM_SMEM_BYTES>>>(x, W, N);

    // Counting sort of edges by dst
    hist_kernel<<<592, 256>>>(ei, E);
    scan1_kernel<<<NB, CHUNK>>>(N);
    scan2_kernel<<<1, 128>>>(NB);
    scan3_kernel<<<NB, CHUNK>>>(N);
    binfill_kernel<<<592, 256>>>(ei, E);

    // Atomic-free gather (writes every output row; no memset of out needed)
    gather_kernel<<<(N + 7) / 8, 256>>>(out, N);
}

// round 7
// speedup vs baseline: 1.3618x; 1.0031x over previous
#include <cuda_runtime.h>
#include <cuda_bf16.h>

// Problem constants (verified against in_sizes at launch)
#define D        128
#define MAX_N    100000
#define MAX_E    3200000
#define CHUNK    1024
#define MAX_BLK  ((MAX_N + CHUNK - 1) / CHUNK)   // 98

// Scratch (__device__ globals per allocation rules)
__device__ float g_h[(size_t)MAX_N * D];      // 51.2 MB: h = x @ W^T
__device__ int   g_count[MAX_N];              // per-dst degree
__device__ int   g_off[MAX_N + 1];            // exclusive offsets
__device__ int   g_cursor[MAX_N];             // fill cursors
__device__ int   g_bsum[MAX_BLK];             // per-block sums
__device__ int   g_boff[MAX_BLK];             // per-block offsets
__device__ int   g_binned_src[MAX_E];         // edges sorted by dst

// ---------------------------------------------------------------------------
// Kernel 1: h = x @ W^T   (fp32 SIMT, W transposed in smem, 4x4 microtile)
// ---------------------------------------------------------------------------
#define WT_LD 132
#define GEMM_SMEM_BYTES ((128 * WT_LD + 32 * 128) * 4)

__global__ void __launch_bounds__(256, 2)
gemm_kernel(const float* __restrict__ x, const float* __restrict__ W, int N) {
    extern __shared__ float smem[];
    float* Wt = smem;                 // [128][WT_LD]  Wt[k][c] = W[c][k]
    float* xs = smem + 128 * WT_LD;   // [32][128]

    const int tid = threadIdx.x;
    const int row0 = blockIdx.x * 32;

    #pragma unroll 4
    for (int i = tid; i < 128 * 128; i += 256) {
        int c = i >> 7, k = i & 127;
        Wt[k * WT_LD + c] = W[i];
    }
    #pragma unroll 4
    for (int i = tid; i < 32 * 128; i += 256) {
        xs[i] = x[(size_t)row0 * D + i];
    }
    __syncthreads();

    const int warp = tid >> 5, lane = tid & 31;
    const int r0 = warp * 4;
    const int c0 = lane * 4;

    float4 acc0 = {0.f,0.f,0.f,0.f};
    float4 acc1 = {0.f,0.f,0.f,0.f};
    float4 acc2 = {0.f,0.f,0.f,0.f};
    float4 acc3 = {0.f,0.f,0.f,0.f};

    #pragma unroll 8
    for (int k0 = 0; k0 < 128; k0 += 4) {
        float4 wv0 = *(const float4*)&Wt[(k0 + 0) * WT_LD + c0];
        float4 wv1 = *(const float4*)&Wt[(k0 + 1) * WT_LD + c0];
        float4 wv2 = *(const float4*)&Wt[(k0 + 2) * WT_LD + c0];
        float4 wv3 = *(const float4*)&Wt[(k0 + 3) * WT_LD + c0];

        float4 xv0 = *(const float4*)&xs[(r0 + 0) * 128 + k0];
        float4 xv1 = *(const float4*)&xs[(r0 + 1) * 128 + k0];
        float4 xv2 = *(const float4*)&xs[(r0 + 2) * 128 + k0];
        float4 xv3 = *(const float4*)&xs[(r0 + 3) * 128 + k0];

        #define STEP(ACC, XV)                                            \
            ACC.x += XV.x * wv0.x; ACC.y += XV.x * wv0.y;                 \
            ACC.z += XV.x * wv0.z; ACC.w += XV.x * wv0.w;                 \
            ACC.x += XV.y * wv1.x; ACC.y += XV.y * wv1.y;                 \
            ACC.z += XV.y * wv1.z; ACC.w += XV.y * wv1.w;                 \
            ACC.x += XV.z * wv2.x; ACC.y += XV.z * wv2.y;                 \
            ACC.z += XV.z * wv2.z; ACC.w += XV.z * wv2.w;                 \
            ACC.x += XV.w * wv3.x; ACC.y += XV.w * wv3.y;                 \
            ACC.z += XV.w * wv3.z; ACC.w += XV.w * wv3.w;
        STEP(acc0, xv0)
        STEP(acc1, xv1)
        STEP(acc2, xv2)
        STEP(acc3, xv3)
        #undef STEP
    }

    float4* hp = (float4*)&g_h[(size_t)(row0 + r0) * D + c0];
    hp[0]           = acc0;
    hp[D / 4]       = acc1;
    hp[2 * (D / 4)] = acc2;
    hp[3 * (D / 4)] = acc3;
}

// ---------------------------------------------------------------------------
// Binning pipeline: counting sort of edges by dst
// ---------------------------------------------------------------------------
__global__ void hist_kernel(const int* __restrict__ ei, int E) {
    int i = blockIdx.x * blockDim.x + threadIdx.x;
    int stride = gridDim.x * blockDim.x;
    for (; i < E; i += stride) {
        atomicAdd(&g_count[ei[E + i]], 1);   // dst row of edge_index
    }
}

// Per-chunk sums of g_count
__global__ void scan1_kernel(int N) {
    __shared__ int s[CHUNK];
    int i = blockIdx.x * CHUNK + threadIdx.x;
    s[threadIdx.x] = (i < N) ? g_count[i] : 0;
    __syncthreads();
    #pragma unroll
    for (int d = CHUNK / 2; d > 0; d >>= 1) {
        if (threadIdx.x < d) s[threadIdx.x] += s[threadIdx.x + d];
        __syncthreads();
    }
    if (threadIdx.x == 0) g_bsum[blockIdx.x] = s[0];
}

// Exclusive scan of block sums (NB <= 128, single block)
__global__ void scan2_kernel(int NB) {
    __shared__ int s[MAX_BLK + 1];
    if (threadIdx.x < NB) s[threadIdx.x] = g_bsum[threadIdx.x];
    __syncthreads();
    if (threadIdx.x == 0) {
        int run = 0;
        for (int b = 0; b < NB; b++) { int v = s[b]; s[b] = run; run += v; }
    }
    __syncthreads();
    if (threadIdx.x < NB) g_boff[threadIdx.x] = s[threadIdx.x];
}

// Per-chunk exclusive scan + base offset -> g_off, g_cursor
__global__ void scan3_kernel(int N) {
    __shared__ int buf0[CHUNK];
    __shared__ int buf1[CHUNK];
    int i = blockIdx.x * CHUNK + threadIdx.x;
    int val = (i < N) ? g_count[i] : 0;

    int* cur = buf0; int* nxt = buf1;
    cur[threadIdx.x] = val;
    __syncthreads();
    #pragma unroll
    for (int d = 1; d < CHUNK; d <<= 1) {             // Hillis-Steele inclusive
        int v = cur[threadIdx.x];
        if (threadIdx.x >= d) v += cur[threadIdx.x - d];
        nxt[threadIdx.x] = v;
        __syncthreads();
        int* t = cur; cur = nxt; nxt = t;
    }
    if (i < N) {
        int excl = cur[threadIdx.x] - val + g_boff[blockIdx.x];
        g_off[i]    = excl;
        g_cursor[i] = excl;
        if (i == N - 1) g_off[N] = excl + val;
    }
}

__global__ void binfill_kernel(const int* __restrict__ ei, int E) {
    int i = blockIdx.x * blockDim.x + threadIdx.x;
    int stride = gridDim.x * blockDim.x;
    for (; i < E; i += stride) {
        int src = ei[i];
        int dst = ei[E + i];
        int pos = atomicAdd(&g_cursor[dst], 1);
        g_binned_src[pos] = src;
    }
}

// ---------------------------------------------------------------------------
// Gather: one warp per destination node, no atomics, single coalesced store.
// Lanes cooperatively load up to 32 bin indices (coalesced), broadcast via
// shfl, accumulate 4-way-interleaved float4s of h rows.
// ---------------------------------------------------------------------------
__global__ void __launch_bounds__(256)
gather_kernel(float* __restrict__ out, int N) {
    const int node = blockIdx.x * 8 + (threadIdx.x >> 5);
    if (node >= N) return;
    const int lane = threadIdx.x & 31;

    const int s = __ldg(&g_off[node]);
    const int e = __ldg(&g_off[node + 1]);

    float4 a0 = {0.f,0.f,0.f,0.f};
    float4 a1 = {0.f,0.f,0.f,0.f};
    float4 a2 = {0.f,0.f,0.f,0.f};
    float4 a3 = {0.f,0.f,0.f,0.f};

    for (int j = s; j < e; j += 32) {
        const int m = min(32, e - j);
        int srcv = (j + lane < e) ? __ldg(&g_binned_src[j + lane]) : 0;

        int b = 0;
        for (; b + 4 <= m; b += 4) {
            int s0 = __shfl_sync(0xFFFFFFFFu, srcv, b);
            int s1 = __shfl_sync(0xFFFFFFFFu, srcv, b + 1);
            int s2 = __shfl_sync(0xFFFFFFFFu, srcv, b + 2);
            int s3 = __shfl_sync(0xFFFFFFFFu, srcv, b + 3);
            float4 v0 = __ldg((const float4*)&g_h[(size_t)s0 * D] + lane);
            float4 v1 = __ldg((const float4*)&g_h[(size_t)s1 * D] + lane);
            float4 v2 = __ldg((const float4*)&g_h[(size_t)s2 * D] + lane);
            float4 v3 = __ldg((const float4*)&g_h[(size_t)s3 * D] + lane);
            a0.x += v0.x; a0.y += v0.y; a0.z += v0.z; a0.w += v0.w;
            a1.x += v1.x; a1.y += v1.y; a1.z += v1.z; a1.w += v1.w;
            a2.x += v2.x; a2.y += v2.y; a2.z += v2.z; a2.w += v2.w;
            a3.x += v3.x; a3.y += v3.y; a3.z += v3.z; a3.w += v3.w;
        }
        for (; b < m; b++) {
            int sb = __shfl_sync(0xFFFFFFFFu, srcv, b);
            float4 v = __ldg((const float4*)&g_h[(size_t)sb * D] + lane);
            a0.x += v.x; a0.y += v.y; a0.z += v.z; a0.w += v.w;
        }
    }

    a0.x += a1.x + a2.x + a3.x;
    a0.y += a1.y + a2.y + a3.y;
    a0.z += a1.z + a2.z + a3.z;
    a0.w += a1.w + a2.w + a3.w;

    *((float4*)&out[(size_t)node * D] + lane) = a0;
}

// ---------------------------------------------------------------------------
extern "C" void kernel_launch(void* const* d_in, const int* in_sizes, int n_in,
                              void* d_out, int out_size) {
    const float* x  = (const float*)d_in[0];   // [N, 128] fp32
    const float* W  = (const float*)d_in[1];   // [128, 128] fp32
    const int*   ei = (const int*)d_in[2];     // [2, E] int32
    float* out = (float*)d_out;                // [N, 128] fp32

    const int N  = in_sizes[0] / D;
    const int E  = in_sizes[2] / 2;
    const int NB = (N + CHUNK - 1) / CHUNK;

    cudaFuncSetAttribute(gemm_kernel,
                         cudaFuncAttributeMaxDynamicSharedMemorySize,
                         GEMM_SMEM_BYTES);

    // Zero the degree histogram (capture-safe: memset on a symbol address).
    void* count_ptr = nullptr;
    cudaGetSymbolAddress(&count_ptr, g_count);
    cudaMemsetAsync(count_ptr, 0, (size_t)N * sizeof(int), 0);

    // GEMM: h = x @ W^T
    gemm_kernel<<<N / 32, 256, GEMM_SMEM_BYTES>>>(x, W, N);

    // Counting sort of edges by dst
    hist_kernel<<<592, 256>>>(ei, E);
    scan1_kernel<<<NB, CHUNK>>>(N);
    scan2_kernel<<<1, 128>>>(NB);
    scan3_kernel<<<NB, CHUNK>>>(N);
    binfill_kernel<<<592, 256>>>(ei, E);

    // Atomic-free gather (writes every output row; no memset of out needed)
    gather_kernel<<<(N + 7) / 8, 256>>>(out, N);
}

// round 8
// speedup vs baseline: 1.3646x; 1.0020x over previous
#include <cuda_runtime.h>
#include <cuda_bf16.h>

// Problem constants (verified against in_sizes at launch)
#define D        128
#define MAX_N    100000
#define MAX_E    3200000
#define CHUNK    1024
#define MAX_BLK  ((MAX_N + CHUNK - 1) / CHUNK)   // 98

// Scratch (__device__ globals per allocation rules)
__device__ float g_h[(size_t)MAX_N * D];      // 51.2 MB: h = x @ W^T
__device__ int   g_count[MAX_N];              // per-dst degree
__device__ int   g_off[MAX_N + 1];            // exclusive offsets
__device__ int   g_cursor[MAX_N];             // fill cursors
__device__ int   g_bsum[MAX_BLK];             // per-block sums
__device__ int   g_boff[MAX_BLK];             // per-block offsets
__device__ int   g_binned_src[MAX_E];         // edges sorted by dst

// ---------------------------------------------------------------------------
// Kernel 1: h = x @ W^T   (fp32 SIMT, W transposed in smem, 4x4 microtile)
// ---------------------------------------------------------------------------
#define WT_LD 132
#define GEMM_SMEM_BYTES ((128 * WT_LD + 32 * 128) * 4)

__global__ void __launch_bounds__(256, 2)
gemm_kernel(const float* __restrict__ x, const float* __restrict__ W, int N) {
    extern __shared__ float smem[];
    float* Wt = smem;                 // [128][WT_LD]  Wt[k][c] = W[c][k]
    float* xs = smem + 128 * WT_LD;   // [32][128]

    const int tid = threadIdx.x;
    const int row0 = blockIdx.x * 32;

    #pragma unroll 4
    for (int i = tid; i < 128 * 128; i += 256) {
        int c = i >> 7, k = i & 127;
        Wt[k * WT_LD + c] = W[i];
    }
    #pragma unroll 4
    for (int i = tid; i < 32 * 128; i += 256) {
        xs[i] = x[(size_t)row0 * D + i];
    }
    __syncthreads();

    const int warp = tid >> 5, lane = tid & 31;
    const int r0 = warp * 4;
    const int c0 = lane * 4;

    float4 acc0 = {0.f,0.f,0.f,0.f};
    float4 acc1 = {0.f,0.f,0.f,0.f};
    float4 acc2 = {0.f,0.f,0.f,0.f};
    float4 acc3 = {0.f,0.f,0.f,0.f};

    #pragma unroll 8
    for (int k0 = 0; k0 < 128; k0 += 4) {
        float4 wv0 = *(const float4*)&Wt[(k0 + 0) * WT_LD + c0];
        float4 wv1 = *(const float4*)&Wt[(k0 + 1) * WT_LD + c0];
        float4 wv2 = *(const float4*)&Wt[(k0 + 2) * WT_LD + c0];
        float4 wv3 = *(const float4*)&Wt[(k0 + 3) * WT_LD + c0];

        float4 xv0 = *(const float4*)&xs[(r0 + 0) * 128 + k0];
        float4 xv1 = *(const float4*)&xs[(r0 + 1) * 128 + k0];
        float4 xv2 = *(const float4*)&xs[(r0 + 2) * 128 + k0];
        float4 xv3 = *(const float4*)&xs[(r0 + 3) * 128 + k0];

        #define STEP(ACC, XV)                                            \
            ACC.x += XV.x * wv0.x; ACC.y += XV.x * wv0.y;                 \
            ACC.z += XV.x * wv0.z; ACC.w += XV.x * wv0.w;                 \
            ACC.x += XV.y * wv1.x; ACC.y += XV.y * wv1.y;                 \
            ACC.z += XV.y * wv1.z; ACC.w += XV.y * wv1.w;                 \
            ACC.x += XV.z * wv2.x; ACC.y += XV.z * wv2.y;                 \
            ACC.z += XV.z * wv2.z; ACC.w += XV.z * wv2.w;                 \
            ACC.x += XV.w * wv3.x; ACC.y += XV.w * wv3.y;                 \
            ACC.z += XV.w * wv3.z; ACC.w += XV.w * wv3.w;
        STEP(acc0, xv0)
        STEP(acc1, xv1)
        STEP(acc2, xv2)
        STEP(acc3, xv3)
        #undef STEP
    }

    float4* hp = (float4*)&g_h[(size_t)(row0 + r0) * D + c0];
    hp[0]           = acc0;
    hp[D / 4]       = acc1;
    hp[2 * (D / 4)] = acc2;
    hp[3 * (D / 4)] = acc3;
}

// ---------------------------------------------------------------------------
// Binning pipeline: counting sort of edges by dst
// ---------------------------------------------------------------------------
__global__ void hist_kernel(const int* __restrict__ ei, int E) {
    int i = blockIdx.x * blockDim.x + threadIdx.x;
    int stride = gridDim.x * blockDim.x;
    for (; i < E; i += stride) {
        atomicAdd(&g_count[ei[E + i]], 1);   // dst row of edge_index
    }
}

// Per-chunk sums of g_count
__global__ void scan1_kernel(int N) {
    __shared__ int s[CHUNK];
    int i = blockIdx.x * CHUNK + threadIdx.x;
    s[threadIdx.x] = (i < N) ? g_count[i] : 0;
    __syncthreads();
    #pragma unroll
    for (int d = CHUNK / 2; d > 0; d >>= 1) {
        if (threadIdx.x < d) s[threadIdx.x] += s[threadIdx.x + d];
        __syncthreads();
    }
    if (threadIdx.x == 0) g_bsum[blockIdx.x] = s[0];
}

// Exclusive scan of block sums (NB <= 128, single block)
__global__ void scan2_kernel(int NB) {
    __shared__ int s[MAX_BLK + 1];
    if (threadIdx.x < NB) s[threadIdx.x] = g_bsum[threadIdx.x];
    __syncthreads();
    if (threadIdx.x == 0) {
        int run = 0;
        for (int b = 0; b < NB; b++) { int v = s[b]; s[b] = run; run += v; }
    }
    __syncthreads();
    if (threadIdx.x < NB) g_boff[threadIdx.x] = s[threadIdx.x];
}

// Per-chunk exclusive scan + base offset -> g_off, g_cursor
__global__ void scan3_kernel(int N) {
    __shared__ int buf0[CHUNK];
    __shared__ int buf1[CHUNK];
    int i = blockIdx.x * CHUNK + threadIdx.x;
    int val = (i < N) ? g_count[i] : 0;

    int* cur = buf0; int* nxt = buf1;
    cur[threadIdx.x] = val;
    __syncthreads();
    #pragma unroll
    for (int d = 1; d < CHUNK; d <<= 1) {             // Hillis-Steele inclusive
        int v = cur[threadIdx.x];
        if (threadIdx.x >= d) v += cur[threadIdx.x - d];
        nxt[threadIdx.x] = v;
        __syncthreads();
        int* t = cur; cur = nxt; nxt = t;
    }
    if (i < N) {
        int excl = cur[threadIdx.x] - val + g_boff[blockIdx.x];
        g_off[i]    = excl;
        g_cursor[i] = excl;
        if (i == N - 1) g_off[N] = excl + val;
    }
}

__global__ void binfill_kernel(const int* __restrict__ ei, int E) {
    int i = blockIdx.x * blockDim.x + threadIdx.x;
    int stride = gridDim.x * blockDim.x;
    for (; i < E; i += stride) {
        int src = ei[i];
        int dst = ei[E + i];
        int pos = atomicAdd(&g_cursor[dst], 1);
        g_binned_src[pos] = src;
    }
}

// ---------------------------------------------------------------------------
// Gather: one warp per destination node, no atomics, single coalesced store.
// Lanes cooperatively load up to 32 bin indices (coalesced), broadcast via
// shfl, accumulate 4-way-interleaved float4s of h rows.
// ---------------------------------------------------------------------------
__global__ void __launch_bounds__(256)
gather_kernel(float* __restrict__ out, int N) {
    const int node = blockIdx.x * 8 + (threadIdx.x >> 5);
    if (node >= N) return;
    const int lane = threadIdx.x & 31;

    const int s = __ldg(&g_off[node]);
    const int e = __ldg(&g_off[node + 1]);

    float4 a0 = {0.f,0.f,0.f,0.f};
    float4 a1 = {0.f,0.f,0.f,0.f};
    float4 a2 = {0.f,0.f,0.f,0.f};
    float4 a3 = {0.f,0.f,0.f,0.f};

    for (int j = s; j < e; j += 32) {
        const int m = min(32, e - j);
        int srcv = (j + lane < e) ? __ldg(&g_binned_src[j + lane]) : 0;

        int b = 0;
        for (; b + 4 <= m; b += 4) {
            int s0 = __shfl_sync(0xFFFFFFFFu, srcv, b);
            int s1 = __shfl_sync(0xFFFFFFFFu, srcv, b + 1);
            int s2 = __shfl_sync(0xFFFFFFFFu, srcv, b + 2);
            int s3 = __shfl_sync(0xFFFFFFFFu, srcv, b + 3);
            float4 v0 = __ldg((const float4*)&g_h[(size_t)s0 * D] + lane);
            float4 v1 = __ldg((const float4*)&g_h[(size_t)s1 * D] + lane);
            float4 v2 = __ldg((const float4*)&g_h[(size_t)s2 * D] + lane);
            float4 v3 = __ldg((const float4*)&g_h[(size_t)s3 * D] + lane);
            a0.x += v0.x; a0.y += v0.y; a0.z += v0.z; a0.w += v0.w;
            a1.x += v1.x; a1.y += v1.y; a1.z += v1.z; a1.w += v1.w;
            a2.x += v2.x; a2.y += v2.y; a2.z += v2.z; a2.w += v2.w;
            a3.x += v3.x; a3.y += v3.y; a3.z += v3.z; a3.w += v3.w;
        }
        for (; b < m; b++) {
            int sb = __shfl_sync(0xFFFFFFFFu, srcv, b);
            float4 v = __ldg((const float4*)&g_h[(size_t)sb * D] + lane);
            a0.x += v.x; a0.y += v.y; a0.z += v.z; a0.w += v.w;
        }
    }

    a0.x += a1.x + a2.x + a3.x;
    a0.y += a1.y + a2.y + a3.y;
    a0.z += a1.z + a2.z + a3.z;
    a0.w += a1.w + a2.w + a3.w;

    *((float4*)&out[(size_t)node * D] + lane) = a0;
}

// ---------------------------------------------------------------------------
extern "C" void kernel_launch(void* const* d_in, const int* in_sizes, int n_in,
                              void* d_out, int out_size) {
    const float* x  = (const float*)d_in[0];   // [N, 128] fp32
    const float* W  = (const float*)d_in[1];   // [128, 128] fp32
    const int*   ei = (const int*)d_in[2];     // [2, E] int32
    float* out = (float*)d_out;                // [N, 128] fp32

    const int N  = in_sizes[0] / D;
    const int E  = in_sizes[2] / 2;
    const int NB = (N + CHUNK - 1) / CHUNK;

    cudaFuncSetAttribute(gemm_kernel,
                         cudaFuncAttributeMaxDynamicSharedMemorySize,
                         GEMM_SMEM_BYTES);

    // Zero the degree histogram (capture-safe: memset on a symbol address).
    void* count_ptr = nullptr;
    cudaGetSymbolAddress(&count_ptr, g_count);
    cudaMemsetAsync(count_ptr, 0, (size_t)N * sizeof(int), 0);

    // GEMM: h = x @ W^T
    gemm_kernel<<<N / 32, 256, GEMM_SMEM_BYTES>>>(x, W, N);

    // Counting sort of edges by dst
    hist_kernel<<<592, 256>>>(ei, E);
    scan1_kernel<<<NB, CHUNK>>>(N);
    scan2_kernel<<<1, 128>>>(NB);
    scan3_kernel<<<NB, CHUNK>>>(N);
    binfill_kernel<<<592, 256>>>(ei, E);

    // Atomic-free gather (writes every output row; no memset of out needed)
    gather_kernel<<<(N + 7) / 8, 256>>>(out, N);
}